// round 13
// baseline (speedup 1.0000x reference)
#include <cuda_runtime.h>
#include <cstdint>

#define TSTEPS 512
#define BATCH  64
#define HB     32          // half-batch stream size
#define IDIM   256
#define HDIM   2048
#define NMT    16          // h tiles (2048/128)
#define NKG    9           // 8 K-slices of W_hat + 1 for W_in
#define NCTA   (NMT*NKG)   // 144 CTAs co-resident
#define KSL    256
#define NT     128         // h per CTA tile
#define APSTR  272         // Ap row stride (272%32==16 -> conflict-free LDS.128)
#define NTHR   256
#define BH     (BATCH*HDIM)
#define HBH    (HB*HDIM)
#define WP_FLOATS (16*4*4*32*4)            // 32768
#define SMEM_BYTES ((WP_FLOATS + HB*APSTR)*4)   // 165,888 B

__device__ float    g_state[3][BH];            // triple-buffered state [b][h]
__device__ float    g_part[2][3][NKG][HBH];    // [half][buf(t%3)][kg][b_local*HDIM+h]
__device__ unsigned g_pflag[2][NCTA];          // produce flags per half (monotonic)
__device__ unsigned g_fflag[2][NCTA];          // finalize flags per half (monotonic)

__device__ __forceinline__ void mma_tf32(float* c, const uint32_t* a, const uint32_t* b) {
    asm volatile(
        "mma.sync.aligned.m16n8k8.row.col.f32.tf32.tf32.f32 "
        "{%0,%1,%2,%3}, {%4,%5,%6,%7}, {%8,%9}, {%0,%1,%2,%3};\n"
        : "+f"(c[0]), "+f"(c[1]), "+f"(c[2]), "+f"(c[3])
        : "r"(a[0]), "r"(a[1]), "r"(a[2]), "r"(a[3]), "r"(b[0]), "r"(b[1]));
}
__device__ __forceinline__ uint32_t rna_tf32(float f) {
    uint32_t u; asm("cvt.rna.tf32.f32 %0, %1;" : "=r"(u) : "f"(f)); return u;
}
__device__ __forceinline__ void relstore(unsigned* p, unsigned v) {
    asm volatile("st.release.gpu.global.u32 [%0], %1;" :: "l"(p), "r"(v) : "memory");
}
__device__ __forceinline__ unsigned acqload(const unsigned* p) {
    unsigned v;
    asm volatile("ld.acquire.gpu.global.u32 %0, [%1];" : "=r"(v) : "l"(p) : "memory");
    return v;
}
__device__ __forceinline__ void poll(const unsigned* p, unsigned tgt) {
    while ((int)(acqload(p) - tgt) < 0) { }
}

__global__ void __launch_bounds__(NTHR, 1)
reservoir_kernel(const float* __restrict__ x,     // [T,B,I]
                 const float* __restrict__ s0,    // [B,H]
                 const float* __restrict__ Win,   // [H,I]
                 const float* __restrict__ What,  // [H,H]
                 float* __restrict__ out)         // [T,B,H]
{
    extern __shared__ float smem[];
    float* Wp = smem;                 // permuted weight fragments
    float* Ap = smem + WP_FLOATS;     // [HB][APSTR] A tile in fragment order

    const int c   = blockIdx.x;
    const int tid = threadIdx.x;
    const int mt  = c % NMT;
    const int kg  = c / NMT;           // 8 = input projection
    const int warp = tid >> 5, lane = tid & 31;
    const int gid  = lane >> 2, tig = lane & 3;
    const int wm   = (warp & 1) * 16;          // 2 warp-rows over M=32 (batch)
    const int wc   = warp >> 1;                // 4 warp-cols over N=128 (h), 32 each

    const unsigned pb0 = *(volatile unsigned*)&g_pflag[0][c];
    const unsigned pb1 = *(volatile unsigned*)&g_pflag[1][c];
    const unsigned fb0 = *(volatile unsigned*)&g_fflag[0][c];
    const unsigned fb1 = *(volatile unsigned*)&g_fflag[1][c];

    // ---- one-time: weight slice -> SMEM in mma-fragment-permuted order ----
    // Wp float4 index (p, wc, ni, lane): floats f=0..3 hold W[n][16p+4f+tig],
    // n = wc*32 + ni*8 + gid, lane = gid*4 + tig.   (validated R7/R10)
    {
        const float* src; int stride;
        if (kg < 8) { src = What + (size_t)mt*NT*HDIM + (size_t)kg*KSL; stride = HDIM; }
        else        { src = Win  + (size_t)mt*NT*IDIM;                  stride = IDIM; }
        for (int i = tid; i < NT*64; i += NTHR) {
            int r = i >> 6, q = i & 63;                // row r, k = 4q..4q+3
            float4 v = *(const float4*)(src + (size_t)r*stride + q*4);
            float* dst = Wp
                + ((((q >> 2)*4 + (r >> 5))*4 + ((r >> 3) & 3))*32 + (r & 7)*4)*4
                + (q & 3);
            dst[0]  = __uint_as_float(rna_tf32(v.x));
            dst[4]  = __uint_as_float(rna_tf32(v.y));
            dst[8]  = __uint_as_float(rna_tf32(v.z));
            dst[12] = __uint_as_float(rna_tf32(v.w));
        }
    }
    // ---- one-time: s0 -> state buffer 2 ----
    if (c < 128) {
        ((float4*)g_state[2])[c*256 + tid] = ((const float4*)s0)[c*256 + tid];
    }
    __syncthreads();
    if (tid == 0) relstore(&g_pflag[0][c], pb0 + 1);
    if (tid < NCTA) poll(&g_pflag[0][tid], pb0 + 1);
    __syncthreads();

    // finalize chunk bounds in float4 groups over [HB x NT] block
    // group g: bl = g>>5, h4 = g&31 -> elements [bl*128 + h4*4 .. +4)
    const int g0 = (kg * (HB*NT/4)) / NKG;
    const int g1 = ((kg + 1) * (HB*NT/4)) / NKG;   // max chunk 114 <= NTHR

    for (int t = 0; t < TSTEPS; ++t) {
        const int pbuf = t % 3;

        // ================= produce: stream h = 0, then 1 =================
        for (int h = 0; h < 2; ++h) {
            const unsigned ftgt = (h ? fb1 : fb0) + (unsigned)t;   // t=0 trivially true
            const unsigned ptgt = (h ? pb1 + 1 : pb0 + 2) + (unsigned)t;

            // wait on ALL finalizers of this half from step t-1
            if (kg < 8 && tid < NCTA) poll(&g_fflag[h][tid], ftgt);
            __syncthreads();

            // ---- A tile -> regs -> SMEM in fragment-permuted order ----
            // Ap[r*APSTR + p*16 + m*4 + j] = tf32(A[r][p*16 + 4j + m])
            const float* src = (kg < 8) ? (g_state[(t+2)%3] + (size_t)h*HB*HDIM + kg*KSL)
                                        : (x + (size_t)t*BATCH*IDIM + (size_t)h*HB*IDIM);
            const int stride = (kg < 8) ? HDIM : IDIM;
            float4 v[8];
            #pragma unroll
            for (int p = 0; p < 8; ++p) {
                int i = tid + p*NTHR, r = i >> 6, c4 = i & 63;
                v[p] = *(const float4*)(src + (size_t)r*stride + c4*4);
            }
            #pragma unroll
            for (int p = 0; p < 8; ++p) {
                int i = tid + p*NTHR, r = i >> 6, c4 = i & 63;
                float* dst = Ap + r*APSTR + (c4 >> 2)*16 + (c4 & 3);
                dst[0]  = __uint_as_float(rna_tf32(v[p].x));
                dst[4]  = __uint_as_float(rna_tf32(v[p].y));
                dst[8]  = __uint_as_float(rna_tf32(v[p].z));
                dst[12] = __uint_as_float(rna_tf32(v[p].w));
            }
            __syncthreads();

            // ---- MMA: D[32,128] = A[32,256] * W[128,256]^T, all LDS.128 ----
            float acc[4][4];
            #pragma unroll
            for (int ni = 0; ni < 4; ++ni)
                #pragma unroll
                for (int q = 0; q < 4; ++q) acc[ni][q] = 0.f;

            const float* apA = Ap + (wm + gid)*APSTR + tig*4;
            #pragma unroll 4
            for (int p = 0; p < 16; ++p) {
                uint4 b4[4];
                #pragma unroll
                for (int ni = 0; ni < 4; ++ni)
                    b4[ni] = *(const uint4*)(Wp + (((p*4 + wc)*4 + ni)*32 + lane)*4);

                const uint4 av0 = *(const uint4*)(apA + p*16);
                const uint4 av1 = *(const uint4*)(apA + 8*APSTR + p*16);
                uint32_t a0[4] = { av0.x, av1.x, av0.y, av1.y };
                uint32_t a1[4] = { av0.z, av1.z, av0.w, av1.w };

                #pragma unroll
                for (int ni = 0; ni < 4; ++ni) {
                    uint32_t b0[2] = { b4[ni].x, b4[ni].y };
                    mma_tf32(acc[ni], a0, b0);
                }
                #pragma unroll
                for (int ni = 0; ni < 4; ++ni) {
                    uint32_t b1[2] = { b4[ni].z, b4[ni].w };
                    mma_tf32(acc[ni], a1, b1);
                }
            }

            // ---- partial store [b_local][h] ----
            {
                float* dst = &g_part[h][pbuf][kg][0] + mt*NT;
                #pragma unroll
                for (int ni = 0; ni < 4; ++ni) {
                    const int row = wm + gid;
                    const int col = wc*32 + ni*8 + tig*2;
                    *(float2*)(dst + (size_t)row*HDIM + col) =
                        make_float2(acc[ni][0], acc[ni][1]);
                    *(float2*)(dst + (size_t)(row+8)*HDIM + col) =
                        make_float2(acc[ni][2], acc[ni][3]);
                }
            }
            __syncthreads();   // stores done; also guards Ap reuse by next stream
            if (tid == 0) relstore(&g_pflag[h][c], ptgt);
        }

        // ================= finalize: stream h = 0, then 1 =================
        for (int h = 0; h < 2; ++h) {
            const unsigned ptgt = (h ? pb1 + 1 : pb0 + 2) + (unsigned)t;
            // wait on ALL producers of this half from step t
            if (tid < NCTA) poll(&g_pflag[h][tid], ptgt);
            __syncthreads();

            {
                const float* P  = &g_part[h][pbuf][0][0];
                const float* sp = g_state[(t+2)%3];
                float*       sn = g_state[t%3];
                float*       op = out + (size_t)t*BH;

                const int g = g0 + tid;
                if (g < g1) {
                    const int bl = g >> 5, h4 = g & 31;
                    const int off = bl*HDIM + mt*NT + h4*4;
                    const int so  = (h*HB + bl)*HDIM + mt*NT + h4*4;
                    float4 s = *(const float4*)(P + off);
                    #pragma unroll
                    for (int k2 = 1; k2 < NKG; ++k2) {
                        float4 w = *(const float4*)(P + (size_t)k2*HBH + off);
                        s.x += w.x; s.y += w.y; s.z += w.z; s.w += w.w;
                    }
                    const float4 spv = *(const float4*)(sp + so);
                    float4 ns;
                    ns.x = 0.5f*(spv.x + tanhf(s.x));
                    ns.y = 0.5f*(spv.y + tanhf(s.y));
                    ns.z = 0.5f*(spv.z + tanhf(s.z));
                    ns.w = 0.5f*(spv.w + tanhf(s.w));
                    *(float4*)(sn + so) = ns;
                    *(float4*)(op + so) = ns;
                }
            }
            __syncthreads();
            if (tid == 0) relstore(&g_fflag[h][c], (h ? fb1 : fb0) + 1 + (unsigned)t);
        }
    }
}

extern "C" void kernel_launch(void* const* d_in, const int* in_sizes, int n_in,
                              void* d_out, int out_size)
{
    (void)in_sizes; (void)n_in; (void)out_size;
    const float* x    = (const float*)d_in[0];
    const float* s0   = (const float*)d_in[1];
    const float* Win  = (const float*)d_in[2];
    const float* What = (const float*)d_in[3];

    cudaFuncSetAttribute(reservoir_kernel,
                         cudaFuncAttributeMaxDynamicSharedMemorySize, SMEM_BYTES);
    reservoir_kernel<<<NCTA, NTHR, SMEM_BYTES>>>(x, s0, Win, What, (float*)d_out);
}

// round 14
// speedup vs baseline: 1.2794x; 1.2794x over previous
#include <cuda_runtime.h>
#include <cstdint>

#define TSTEPS 512
#define BATCH  64
#define HB     32          // half-batch stream size
#define IDIM   256
#define HDIM   2048
#define NMT    16          // h tiles (2048/128)
#define NKG    9           // 8 K-slices of W_hat + 1 for W_in
#define NCTA   (NMT*NKG)   // 144 CTAs co-resident
#define KSL    256
#define NT     128         // h per CTA tile
#define APAD   260
#define NTHR   256
#define BH     (BATCH*HDIM)
#define HBH    (HB*HDIM)
// SMEM: Wp (permuted weights) + single A buffer
#define WP_FLOATS (16*4*4*32*4)            // 32768
#define SMEM_BYTES ((WP_FLOATS + HB*APAD)*4)   // 164,352 B

__device__ float    g_state[3][BH];            // triple-buffered state [b][h]
__device__ float    g_part[2][3][NKG][HBH];    // [half][buf(t%3)][kg][b_local*HDIM+h]
__device__ unsigned g_pflag[2][NCTA];          // produce flags per half (monotonic)
__device__ unsigned g_fflag[2][NCTA];          // finalize flags per half (monotonic)

__device__ __forceinline__ void mma_tf32(float* c, const uint32_t* a, const uint32_t* b) {
    asm volatile(
        "mma.sync.aligned.m16n8k8.row.col.f32.tf32.tf32.f32 "
        "{%0,%1,%2,%3}, {%4,%5,%6,%7}, {%8,%9}, {%0,%1,%2,%3};\n"
        : "+f"(c[0]), "+f"(c[1]), "+f"(c[2]), "+f"(c[3])
        : "r"(a[0]), "r"(a[1]), "r"(a[2]), "r"(a[3]), "r"(b[0]), "r"(b[1]));
}
__device__ __forceinline__ uint32_t rna_tf32(float f) {
    uint32_t u; asm("cvt.rna.tf32.f32 %0, %1;" : "=r"(u) : "f"(f)); return u;
}
__device__ __forceinline__ void relstore(unsigned* p, unsigned v) {
    asm volatile("st.release.gpu.global.u32 [%0], %1;" :: "l"(p), "r"(v) : "memory");
}
__device__ __forceinline__ unsigned acqload(const unsigned* p) {
    unsigned v;
    asm volatile("ld.acquire.gpu.global.u32 %0, [%1];" : "=r"(v) : "l"(p) : "memory");
    return v;
}
__device__ __forceinline__ void poll(const unsigned* p, unsigned tgt) {
    while ((int)(acqload(p) - tgt) < 0) { }
}

__global__ void __launch_bounds__(NTHR, 1)
reservoir_kernel(const float* __restrict__ x,     // [T,B,I]
                 const float* __restrict__ s0,    // [B,H]
                 const float* __restrict__ Win,   // [H,I]
                 const float* __restrict__ What,  // [H,H]
                 float* __restrict__ out)         // [T,B,H]
{
    extern __shared__ float smem[];
    float* Wp = smem;                 // permuted weight fragments
    float* As = smem + WP_FLOATS;     // [HB][APAD] A tile (reused per stream)

    const int c   = blockIdx.x;
    const int tid = threadIdx.x;
    const int mt  = c % NMT;
    const int kg  = c / NMT;           // 8 = input projection
    const int warp = tid >> 5, lane = tid & 31;
    const int gid  = lane >> 2, tig = lane & 3;
    const int wm   = (warp & 1) * 16;          // 2 warp-rows over M=32 (batch)
    const int wc   = warp >> 1;                // 4 warp-cols over N=128 (h), 32 each

    const unsigned pb0 = *(volatile unsigned*)&g_pflag[0][c];
    const unsigned pb1 = *(volatile unsigned*)&g_pflag[1][c];
    const unsigned fb0 = *(volatile unsigned*)&g_fflag[0][c];
    const unsigned fb1 = *(volatile unsigned*)&g_fflag[1][c];

    // ---- one-time: weight slice -> SMEM in mma-fragment-permuted order ----
    // Wp float4 index (p, wc, ni, lane): floats f=0..3 hold W[n][16p+4f+tig],
    // n = wc*32 + ni*8 + gid, lane = gid*4 + tig.   (validated R7/R10)
    {
        const float* src; int stride;
        if (kg < 8) { src = What + (size_t)mt*NT*HDIM + (size_t)kg*KSL; stride = HDIM; }
        else        { src = Win  + (size_t)mt*NT*IDIM;                  stride = IDIM; }
        for (int i = tid; i < NT*64; i += NTHR) {
            int r = i >> 6, q = i & 63;                // row r, k = 4q..4q+3
            float4 v = *(const float4*)(src + (size_t)r*stride + q*4);
            float* dst = Wp
                + ((((q >> 2)*4 + (r >> 5))*4 + ((r >> 3) & 3))*32 + (r & 7)*4)*4
                + (q & 3);
            dst[0]  = __uint_as_float(rna_tf32(v.x));
            dst[4]  = __uint_as_float(rna_tf32(v.y));
            dst[8]  = __uint_as_float(rna_tf32(v.z));
            dst[12] = __uint_as_float(rna_tf32(v.w));
        }
    }
    // ---- one-time: s0 -> state buffer 2 ----
    if (c < 128) {
        ((float4*)g_state[2])[c*256 + tid] = ((const float4*)s0)[c*256 + tid];
    }
    __syncthreads();
    if (tid == 0) relstore(&g_pflag[0][c], pb0 + 1);
    if (tid < NCTA) poll(&g_pflag[0][tid], pb0 + 1);
    __syncthreads();

    // finalize chunk bounds in float4 groups over [HB x NT] block
    // group g: bl = g>>5, h4 = g&31 -> elements [bl*128 + h4*4 .. +4)
    const int g0 = (kg * (HB*NT/4)) / NKG;
    const int g1 = ((kg + 1) * (HB*NT/4)) / NKG;   // max chunk 114 <= NTHR

    for (int t = 0; t < TSTEPS; ++t) {
        const int pbuf = t % 3;

        // ================= produce: stream h = 0, then 1 =================
        for (int h = 0; h < 2; ++h) {
            const unsigned ftgt = (h ? fb1 : fb0) + (unsigned)t;   // t=0 trivially true
            const unsigned ptgt = (h ? pb1 + 1 : pb0 + 2) + (unsigned)t;

            // wait on ALL finalizers of this half from step t-1
            if (kg < 8 && tid < NCTA) poll(&g_fflag[h][tid], ftgt);
            __syncthreads();

            // ---- A tile: state half-slice (or x_t half) -> regs -> SMEM ----
            const float* src = (kg < 8) ? (g_state[(t+2)%3] + (size_t)h*HB*HDIM + kg*KSL)
                                        : (x + (size_t)t*BATCH*IDIM + (size_t)h*HB*IDIM);
            const int stride = (kg < 8) ? HDIM : IDIM;
            float4 v[8];
            #pragma unroll
            for (int p = 0; p < 8; ++p) {
                int i = tid + p*NTHR, r = i >> 6, c4 = i & 63;
                v[p] = *(const float4*)(src + (size_t)r*stride + c4*4);
            }
            #pragma unroll
            for (int p = 0; p < 8; ++p) {
                int i = tid + p*NTHR, r = i >> 6, c4 = i & 63;
                uint4 u;
                u.x = rna_tf32(v[p].x); u.y = rna_tf32(v[p].y);
                u.z = rna_tf32(v[p].z); u.w = rna_tf32(v[p].w);
                *(uint4*)(As + r*APAD + c4*4) = u;
            }
            __syncthreads();

            // ---- MMA: D[32,128] = As[32,256] * Wp^T (R10 loop, proven) ----
            float acc[4][4];
            #pragma unroll
            for (int ni = 0; ni < 4; ++ni)
                #pragma unroll
                for (int q = 0; q < 4; ++q) acc[ni][q] = 0.f;

            #pragma unroll 4
            for (int p = 0; p < 16; ++p) {
                uint4 b4[4];
                #pragma unroll
                for (int ni = 0; ni < 4; ++ni)
                    b4[ni] = *(const uint4*)(Wp + (((p*4 + wc)*4 + ni)*32 + lane)*4);

                const float* ap = As + (wm + gid)*APAD + p*16 + tig;
                uint32_t a0[4], a1[4];
                a0[0] = __float_as_uint(ap[0]);
                a0[1] = __float_as_uint(ap[8*APAD]);
                a0[2] = __float_as_uint(ap[4]);
                a0[3] = __float_as_uint(ap[8*APAD + 4]);
                a1[0] = __float_as_uint(ap[8]);
                a1[1] = __float_as_uint(ap[8*APAD + 8]);
                a1[2] = __float_as_uint(ap[12]);
                a1[3] = __float_as_uint(ap[8*APAD + 12]);

                #pragma unroll
                for (int ni = 0; ni < 4; ++ni) {
                    uint32_t b0[2] = { b4[ni].x, b4[ni].y };
                    mma_tf32(acc[ni], a0, b0);
                }
                #pragma unroll
                for (int ni = 0; ni < 4; ++ni) {
                    uint32_t b1[2] = { b4[ni].z, b4[ni].w };
                    mma_tf32(acc[ni], a1, b1);
                }
            }

            // ---- partial store [b_local][h] straight from accumulators ----
            {
                float* dst = &g_part[h][pbuf][kg][0] + mt*NT;
                #pragma unroll
                for (int ni = 0; ni < 4; ++ni) {
                    const int row = wm + gid;
                    const int col = wc*32 + ni*8 + tig*2;
                    *(float2*)(dst + (size_t)row*HDIM + col) =
                        make_float2(acc[ni][0], acc[ni][1]);
                    *(float2*)(dst + (size_t)(row+8)*HDIM + col) =
                        make_float2(acc[ni][2], acc[ni][3]);
                }
            }
            __syncthreads();   // stores done; also guards As reuse by next stream
            if (tid == 0) relstore(&g_pflag[h][c], ptgt);
        }

        // ================= finalize: stream h = 0, then 1 =================
        for (int h = 0; h < 2; ++h) {
            const unsigned ptgt = (h ? pb1 + 1 : pb0 + 2) + (unsigned)t;
            // wait on ALL producers of this half from step t
            if (tid < NCTA) poll(&g_pflag[h][tid], ptgt);
            __syncthreads();

            float4 ns;
            int so = -1;
            {
                const float* P  = &g_part[h][pbuf][0][0];
                const float* sp = g_state[(t+2)%3];
                float*       sn = g_state[t%3];

                const int g = g0 + tid;
                if (g < g1) {
                    const int bl = g >> 5, h4 = g & 31;
                    const int off = bl*HDIM + mt*NT + h4*4;
                    so = (h*HB + bl)*HDIM + mt*NT + h4*4;
                    float4 s = *(const float4*)(P + off);
                    #pragma unroll
                    for (int k2 = 1; k2 < NKG; ++k2) {
                        float4 w = *(const float4*)(P + (size_t)k2*HBH + off);
                        s.x += w.x; s.y += w.y; s.z += w.z; s.w += w.w;
                    }
                    const float4 spv = *(const float4*)(sp + so);
                    ns.x = 0.5f*(spv.x + tanhf(s.x));
                    ns.y = 0.5f*(spv.y + tanhf(s.y));
                    ns.z = 0.5f*(spv.z + tanhf(s.z));
                    ns.w = 0.5f*(spv.w + tanhf(s.w));
                    *(float4*)(sn + so) = ns;
                }
            }
            __syncthreads();
            if (tid == 0) relstore(&g_fflag[h][c], (h ? fb1 : fb0) + 1 + (unsigned)t);

            // ---- out writes off the release chain (never read in-kernel) ----
            if (so >= 0) {
                *(float4*)(out + (size_t)t*BH + so) = ns;
            }
        }
    }
}

extern "C" void kernel_launch(void* const* d_in, const int* in_sizes, int n_in,
                              void* d_out, int out_size)
{
    (void)in_sizes; (void)n_in; (void)out_size;
    const float* x    = (const float*)d_in[0];
    const float* s0   = (const float*)d_in[1];
    const float* Win  = (const float*)d_in[2];
    const float* What = (const float*)d_in[3];

    cudaFuncSetAttribute(reservoir_kernel,
                         cudaFuncAttributeMaxDynamicSharedMemorySize, SMEM_BYTES);
    reservoir_kernel<<<NCTA, NTHR, SMEM_BYTES>>>(x, s0, Win, What, (float*)d_out);
}